// round 14
// baseline (speedup 1.0000x reference)
#include <cuda_runtime.h>
#include <cuda_bf16.h>
#include <cuda_fp16.h>
#include <cstdint>
#include <math.h>

#define Bsz 32
#define Cch 128
#define OCn 128
#define En  8
#define Tn  256
#define HIDn 64
#define UPn 256
#define Rn  32
#define GHn 8
#define PADW  66
#define PROWS (66*66)
#define WSCALE 256.0f
#define WSCALE_INV 0.00390625f

// ---- device scratch ----
__device__ float g_ps [Bsz * 64 * Cch];
__device__ float g_ps2[Bsz * 64 * Cch];
__device__ float g_rw[Bsz * En];
__device__ __align__(16) __half g_wh[Bsz * 9 * 2 * OCn * 64];       // mixed weights, fp16, x256
__device__ __align__(16) __half g_xt[(size_t)Bsz * PROWS * Cch];    // x^T padded, fp16

// ---- PTX helpers (baseline PTX only) ----
__device__ __forceinline__ uint32_t smem_u32(const void* p) {
    uint32_t a;
    asm("{ .reg .u64 t; cvta.to.shared.u64 t, %1; cvt.u32.u64 %0, t; }" : "=r"(a) : "l"(p));
    return a;
}
__device__ __forceinline__ void cp16(uint32_t dst, const void* src) {
    asm volatile("cp.async.cg.shared.global [%0], [%1], 16;" :: "r"(dst), "l"(src));
}
__device__ __forceinline__ void cp_commit() {
    asm volatile("cp.async.commit_group;" ::: "memory");
}
__device__ __forceinline__ void cp_wait1() {
    asm volatile("cp.async.wait_group 1;" ::: "memory");
}
__device__ __forceinline__ void cp_wait0() {
    asm volatile("cp.async.wait_group 0;" ::: "memory");
}
__device__ __forceinline__ void ldsm4(uint32_t* r, uint32_t addr) {
    asm volatile("ldmatrix.sync.aligned.m8n8.x4.shared.b16 {%0,%1,%2,%3}, [%4];"
                 : "=r"(r[0]), "=r"(r[1]), "=r"(r[2]), "=r"(r[3]) : "r"(addr));
}
__device__ __forceinline__ void mma_fp16(float* d, const uint32_t* a, const uint32_t* b) {
    asm volatile(
        "mma.sync.aligned.m16n8k16.row.col.f32.f16.f16.f32 "
        "{%0,%1,%2,%3}, {%4,%5,%6,%7}, {%8,%9}, {%0,%1,%2,%3};"
        : "+f"(d[0]), "+f"(d[1]), "+f"(d[2]), "+f"(d[3])
        : "r"(a[0]), "r"(a[1]), "r"(a[2]), "r"(a[3]), "r"(b[0]), "r"(b[1]));
}
__device__ __forceinline__ uint32_t swz(uint32_t off) { return off ^ ((off >> 3) & 0x70); }

// ============================================================
// Launch 1: prep = transpose + partial stats + border zeroing
// ============================================================
__global__ void prep_kernel(const float* __restrict__ x) {
    __shared__ float s[128][65];
    int y = blockIdx.x, b = blockIdx.y, tid = threadIdx.x;
    const float* xb = x + (size_t)b * Cch * 4096;
    for (int i = tid; i < 8192; i += 256) {
        int c = i >> 6, xx = i & 63;
        s[c][xx] = xb[(size_t)c * 4096 + y * 64 + xx];
    }
    __syncthreads();

    if (tid < 128) {
        float s1 = 0.f, s2 = 0.f;
        #pragma unroll 8
        for (int xx = 0; xx < 64; xx++) {
            float v = s[tid][xx];
            s1 += v; s2 += v * v;
        }
        int d = (b * 64 + y) * 128 + tid;
        g_ps[d] = s1; g_ps2[d] = s2;
    }

    size_t base = ((size_t)b * PROWS + (size_t)(y + 1) * PADW + 1) * 128;
    for (int i = tid; i < 4096; i += 256) {
        int px = i >> 6, cc = (i & 63) * 2;
        __half2 hp;
        hp.x = __float2half(s[cc][px]);
        hp.y = __float2half(s[cc + 1][px]);
        *(__half2*)(g_xt + base + (size_t)px * 128 + cc) = hp;
    }

    __half z = __float2half(0.f);
    if (tid < 128) {
        size_t r = ((size_t)b * PROWS + (size_t)(y + 1) * PADW) * 128;
        g_xt[r + tid] = z;
        g_xt[r + 65 * 128 + tid] = z;
    }
    if (y == 0) {
        size_t r = (size_t)b * PROWS * 128;
        for (int i = tid; i < 66 * 128; i += 256) g_xt[r + i] = z;
    }
    if (y == 63) {
        size_t r = ((size_t)b * PROWS + 65 * PADW) * 128;
        for (int i = tid; i < 66 * 128; i += 256) g_xt[r + i] = z;
    }
}

// ============================================================
// Launch 2: router (finalizes stats from partials)
// ============================================================
__global__ void router_kernel(
    const float* __restrict__ time_emb,
    const float* __restrict__ W_q,  const float* __restrict__ W_k,  const float* __restrict__ W_v,
    const float* __restrict__ W_g,  const float* __restrict__ b_g,
    const float* __restrict__ W_a1, const float* __restrict__ b_a1, const float* __restrict__ W_a2,
    const float* __restrict__ W_b1, const float* __restrict__ b_b1, const float* __restrict__ W_b2,
    const float* __restrict__ W_d,  const float* __restrict__ W_out)
{
    int b = blockIdx.x, tid = threadIdx.x;
    __shared__ float te[Tn], sts[2*Cch], xh[HIDn], a1v[GHn], b1v[GHn],
                     tv[Rn], hv[UPn], xm[HIDn], lg[En];
    te[tid] = time_emb[b * Tn + tid];
    if (tid < Cch) {
        float s1 = 0.f, s2 = 0.f;
        for (int y = 0; y < 64; y++) {
            int d = (b * 64 + y) * 128 + tid;
            s1 += g_ps[d]; s2 += g_ps2[d];
        }
        float mu  = s1 * (1.f / 4096.f);
        float var = s2 * (1.f / 4096.f) - mu * mu;
        sts[tid]       = mu;
        sts[Cch + tid] = sqrtf(fmaxf(var, 0.f)) + 1e-6f;
    }
    __syncthreads();
    if (tid < HIDn) {
        float q = 0.f, k = 0.f, v = 0.f;
        for (int j = 0; j < Tn; j++) q += W_q[tid*Tn+j] * te[j];
        for (int j = 0; j < 2*Cch; j++) {
            float s = sts[j];
            k += W_k[tid*2*Cch+j] * s;
            v += W_v[tid*2*Cch+j] * s;
        }
        xh[tid] = v / (1.f + expf(-(q*k)));
    }
    __syncthreads();
    if (tid < GHn) {
        float sa = b_a1[tid], sb = b_b1[tid];
        for (int i = 0; i < HIDn; i++) { sa += W_a1[tid*HIDn+i]*xh[i]; sb += W_b1[tid*HIDn+i]*xh[i]; }
        a1v[tid] = sa / (1.f + expf(-sa));
        b1v[tid] = sb / (1.f + expf(-sb));
    }
    __syncthreads();
    if (tid < Rn) {
        float acc = 0.f;
        for (int i = 0; i < HIDn; i++) {
            const float* wr = W_a2 + (size_t)(i*Rn + tid)*GHn;
            float ai = 0.f;
            #pragma unroll
            for (int g = 0; g < GHn; g++) ai += wr[g]*a1v[g];
            acc += xh[i]*ai;
        }
        tv[tid] = acc;
    }
    __syncthreads();
    {
        float gate = b_g[tid];
        for (int i = 0; i < HIDn; i++) gate += W_g[tid*HIDn+i]*xh[i];
        float dyn = 0.f;
        for (int r = 0; r < Rn; r++) {
            const float* wr = W_b2 + (size_t)(r*UPn + tid)*GHn;
            float bm = 0.f;
            #pragma unroll
            for (int g = 0; g < GHn; g++) bm += wr[g]*b1v[g];
            dyn += tv[r]*bm;
        }
        hv[tid] = (gate / (1.f + expf(-gate))) * dyn;
    }
    __syncthreads();
    if (tid < HIDn) {
        float m = xh[tid];
        for (int o = 0; o < UPn; o++) m += W_d[tid*UPn+o]*hv[o];
        xm[tid] = m;
    }
    __syncthreads();
    if (tid < En) {
        float l = 0.f;
        for (int i = 0; i < HIDn; i++) l += W_out[tid*HIDn+i]*xm[i];
        lg[tid] = l;
    }
    __syncthreads();
    if (tid == 0) {
        float mx = lg[0];
        for (int e = 1; e < En; e++) mx = fmaxf(mx, lg[e]);
        float ex[En]; float s = 0.f;
        for (int e = 0; e < En; e++) { ex[e] = expf(lg[e]-mx); s += ex[e]; }
        float inv = 1.f / s;
        for (int e = 0; e < En; e++) g_rw[b*En+e] = ex[e]*inv;
    }
}

// ============================================================
// Launch 3: mix -> fp16 tiles (x256)  [b][tap][chunk][oc][64c]
// ============================================================
__global__ void mix_kernel(const float* __restrict__ expert_w) {
    __shared__ float srw[Bsz * En];
    int tid = threadIdx.x;
    srw[tid] = g_rw[tid];
    __syncthreads();

    int idx = blockIdx.x * 256 + tid;
    int oc = idx >> 7, c = idx & 127;
    int b0 = blockIdx.y * 8;

    float w[En][9];
    #pragma unroll
    for (int e = 0; e < En; e++) {
        const float* src = expert_w + ((size_t)(e * 128 + oc) * 128 + c) * 9;
        #pragma unroll
        for (int k = 0; k < 9; k++) w[e][k] = src[k];
    }

    int cx = c >> 6, cl = c & 63;
    for (int b = b0; b < b0 + 8; b++) {
        float rw[En];
        #pragma unroll
        for (int e = 0; e < En; e++) rw[e] = srw[b * En + e];
        #pragma unroll
        for (int k = 0; k < 9; k++) {
            float acc = 0.f;
            #pragma unroll
            for (int e = 0; e < En; e++) acc += rw[e] * w[e][k];
            int d = ((b * 9 + k) * 2 + cx) * 8192 + oc * 64 + cl;
            g_wh[d] = __float2half(acc * WSCALE);
        }
    }
}

// ============================================================
// Launch 4: conv via mma.sync fp16
// CTA = (4 image rows, b), 256 threads (8 warps, 2x4), warp tile 64oc x 64px.
// Stage 48KB (A16|B32), 2 stages = 96KB -> 2 CTAs/SM (16 warps/SM).
// ============================================================
#define STG  49152
#define SA   0
#define SB   16384
#define CONV_SMEM (2*STG)

__global__ void __launch_bounds__(256)
conv_mma_kernel(float* __restrict__ out)
{
    extern __shared__ char dsm[];
    const uint32_t sb = smem_u32(dsm);
    const int tid  = threadIdx.x;
    const int lane = tid & 31;
    const int wid  = tid >> 5;
    const int wm   = wid & 1;          // 64-oc block
    const int wn   = wid >> 1;         // 0..3 : 64-px block (= image row select)
    const int b    = blockIdx.y;
    const int y0   = blockIdx.x * 4;   // four image rows per CTA

    const char* x_base = (const char*)g_xt + (size_t)b * PROWS * 256;

    float acc[4][8][4];
    #pragma unroll
    for (int mi = 0; mi < 4; mi++)
        #pragma unroll
        for (int ni = 0; ni < 8; ni++)
            #pragma unroll
            for (int k = 0; k < 4; k++) acc[mi][ni][k] = 0.f;

    auto load_chunk = [&](int ch, int s) {
        int tap = ch >> 1, cx = ch & 1;
        int dy = tap / 3, dx = tap % 3;
        uint32_t so = sb + s * STG;
        const char* ah = (const char*)g_wh + (size_t)((b*9 + tap)*2 + cx) * 16384;
        for (int i = tid; i < 1024; i += 256) {
            cp16(so + SA + swz((uint32_t)i * 16), ah + i * 16);
        }
        // B: 256 px rows (4 image rows) x 128B
        for (int i = tid; i < 2048; i += 256) {
            int lr = i >> 3, u = i & 7;
            int p = (y0 + (lr >> 6) + dy) * PADW + dx + (lr & 63);
            size_t g = (size_t)p * 256 + cx * 128 + u * 16;
            cp16(so + SB + swz((uint32_t)i * 16), x_base + g);
        }
        cp_commit();
    };

    load_chunk(0, 0);

    for (int ch = 0; ch < 18; ch++) {
        if (ch < 17) load_chunk(ch + 1, (ch + 1) & 1);
        if (ch < 17) cp_wait1(); else cp_wait0();
        __syncthreads();

        uint32_t so = sb + (ch & 1) * STG;
        int arow = wm * 64 + (lane & 15);
        int acol16 = (lane >> 4) * 16;
        int brow = wn * 64 + ((lane >> 4) << 3) + (lane & 7);
        int bcol16 = ((lane >> 3) & 1) * 16;

        #pragma unroll
        for (int ks = 0; ks < 4; ks++) {
            uint32_t ah[4][4], bh[8][2];
            #pragma unroll
            for (int mi = 0; mi < 4; mi++) {
                uint32_t off = swz((uint32_t)(arow + mi * 16) * 128 + ks * 32 + acol16);
                ldsm4(ah[mi], so + SA + off);
            }
            #pragma unroll
            for (int np = 0; np < 4; np++) {
                uint32_t off = swz((uint32_t)(brow + np * 16) * 128 + ks * 32 + bcol16);
                uint32_t t[4];
                ldsm4(t, so + SB + off);
                bh[2*np][0] = t[0]; bh[2*np][1] = t[1];
                bh[2*np+1][0] = t[2]; bh[2*np+1][1] = t[3];
            }
            #pragma unroll
            for (int mi = 0; mi < 4; mi++)
                #pragma unroll
                for (int ni = 0; ni < 8; ni++)
                    mma_fp16(acc[mi][ni], ah[mi], bh[ni]);
        }
        __syncthreads();
    }

    // epilogue: y = y0 + wn, x = ni*8 + 2q
    int gid = lane >> 2, q = lane & 3;
    int y = y0 + wn;
    #pragma unroll
    for (int mi = 0; mi < 4; mi++) {
        int oc = wm * 64 + mi * 16 + gid;
        #pragma unroll
        for (int ni = 0; ni < 8; ni++) {
            int xc = ni * 8 + 2 * q;
            size_t base0 = (((size_t)(b * 128 + oc)) * 64 + y) * 64 + xc;
            float2 v0 = make_float2(acc[mi][ni][0] * WSCALE_INV, acc[mi][ni][1] * WSCALE_INV);
            float2 v1 = make_float2(acc[mi][ni][2] * WSCALE_INV, acc[mi][ni][3] * WSCALE_INV);
            *(float2*)(out + base0)          = v0;
            *(float2*)(out + base0 + 8*4096) = v1;   // oc + 8
        }
    }
}

// ============================================================
extern "C" void kernel_launch(void* const* d_in, const int* in_sizes, int n_in,
                              void* d_out, int out_size)
{
    const float* x        = (const float*)d_in[0];
    const float* time_emb = (const float*)d_in[1];
    const float* expert_w = (const float*)d_in[2];
    const float* W_q  = (const float*)d_in[3];
    const float* W_k  = (const float*)d_in[4];
    const float* W_v  = (const float*)d_in[5];
    const float* W_g  = (const float*)d_in[6];
    const float* b_g  = (const float*)d_in[7];
    const float* W_a1 = (const float*)d_in[8];
    const float* b_a1 = (const float*)d_in[9];
    const float* W_a2 = (const float*)d_in[10];
    const float* W_b1 = (const float*)d_in[11];
    const float* b_b1 = (const float*)d_in[12];
    const float* W_b2 = (const float*)d_in[13];
    const float* W_d  = (const float*)d_in[14];
    const float* W_out= (const float*)d_in[15];
    float* out = (float*)d_out;

    cudaFuncSetAttribute(conv_mma_kernel,
                         cudaFuncAttributeMaxDynamicSharedMemorySize, CONV_SMEM);

    prep_kernel<<<dim3(64, Bsz), 256>>>(x);
    router_kernel<<<Bsz, 256>>>(time_emb, W_q, W_k, W_v, W_g, b_g,
                                W_a1, b_a1, W_a2, W_b1, b_b1, W_b2, W_d, W_out);
    mix_kernel<<<dim3(64, 4), 256>>>(expert_w);
    conv_mma_kernel<<<dim3(16, Bsz), 256, CONV_SMEM>>>(out);
}

// round 15
// speedup vs baseline: 1.1065x; 1.1065x over previous
#include <cuda_runtime.h>
#include <cuda_bf16.h>
#include <cuda_fp16.h>
#include <cstdint>
#include <math.h>

#define Bsz 32
#define Cch 128
#define OCn 128
#define En  8
#define Tn  256
#define HIDn 64
#define UPn 256
#define Rn  32
#define GHn 8
#define PADW  66
#define PROWS (66*66)
#define WSCALE 256.0f
#define WSCALE_INV 0.00390625f

// ---- device scratch ----
__device__ float g_ps [Bsz * 64 * Cch];
__device__ float g_ps2[Bsz * 64 * Cch];
__device__ float g_rw[Bsz * En];
__device__ __align__(16) __half g_wh[Bsz * 9 * 2 * OCn * 64];       // mixed weights, fp16, x256
__device__ __align__(16) __half g_xt[(size_t)Bsz * PROWS * Cch];    // x^T padded, fp16

// ---- PTX helpers (baseline PTX only) ----
__device__ __forceinline__ uint32_t smem_u32(const void* p) {
    uint32_t a;
    asm("{ .reg .u64 t; cvta.to.shared.u64 t, %1; cvt.u32.u64 %0, t; }" : "=r"(a) : "l"(p));
    return a;
}
__device__ __forceinline__ void cp16(uint32_t dst, const void* src) {
    asm volatile("cp.async.cg.shared.global [%0], [%1], 16;" :: "r"(dst), "l"(src));
}
__device__ __forceinline__ void cp_commit() {
    asm volatile("cp.async.commit_group;" ::: "memory");
}
__device__ __forceinline__ void cp_wait1() {
    asm volatile("cp.async.wait_group 1;" ::: "memory");
}
__device__ __forceinline__ void cp_wait0() {
    asm volatile("cp.async.wait_group 0;" ::: "memory");
}
__device__ __forceinline__ void ldsm4(uint32_t* r, uint32_t addr) {
    asm volatile("ldmatrix.sync.aligned.m8n8.x4.shared.b16 {%0,%1,%2,%3}, [%4];"
                 : "=r"(r[0]), "=r"(r[1]), "=r"(r[2]), "=r"(r[3]) : "r"(addr));
}
__device__ __forceinline__ void mma_fp16(float* d, const uint32_t* a, const uint32_t* b) {
    asm volatile(
        "mma.sync.aligned.m16n8k16.row.col.f32.f16.f16.f32 "
        "{%0,%1,%2,%3}, {%4,%5,%6,%7}, {%8,%9}, {%0,%1,%2,%3};"
        : "+f"(d[0]), "+f"(d[1]), "+f"(d[2]), "+f"(d[3])
        : "r"(a[0]), "r"(a[1]), "r"(a[2]), "r"(a[3]), "r"(b[0]), "r"(b[1]));
}
__device__ __forceinline__ uint32_t swz(uint32_t off) { return off ^ ((off >> 3) & 0x70); }

// ============================================================
// Launch 1: prep = transpose + partial stats + border zeroing
// ============================================================
__global__ void prep_kernel(const float* __restrict__ x) {
    __shared__ float s[128][65];
    int y = blockIdx.x, b = blockIdx.y, tid = threadIdx.x;
    const float* xb = x + (size_t)b * Cch * 4096;
    for (int i = tid; i < 8192; i += 256) {
        int c = i >> 6, xx = i & 63;
        s[c][xx] = xb[(size_t)c * 4096 + y * 64 + xx];
    }
    __syncthreads();

    if (tid < 128) {
        float s1 = 0.f, s2 = 0.f;
        #pragma unroll 8
        for (int xx = 0; xx < 64; xx++) {
            float v = s[tid][xx];
            s1 += v; s2 += v * v;
        }
        int d = (b * 64 + y) * 128 + tid;
        g_ps[d] = s1; g_ps2[d] = s2;
    }

    size_t base = ((size_t)b * PROWS + (size_t)(y + 1) * PADW + 1) * 128;
    for (int i = tid; i < 4096; i += 256) {
        int px = i >> 6, cc = (i & 63) * 2;
        __half2 hp;
        hp.x = __float2half(s[cc][px]);
        hp.y = __float2half(s[cc + 1][px]);
        *(__half2*)(g_xt + base + (size_t)px * 128 + cc) = hp;
    }

    __half z = __float2half(0.f);
    if (tid < 128) {
        size_t r = ((size_t)b * PROWS + (size_t)(y + 1) * PADW) * 128;
        g_xt[r + tid] = z;
        g_xt[r + 65 * 128 + tid] = z;
    }
    if (y == 0) {
        size_t r = (size_t)b * PROWS * 128;
        for (int i = tid; i < 66 * 128; i += 256) g_xt[r + i] = z;
    }
    if (y == 63) {
        size_t r = ((size_t)b * PROWS + 65 * PADW) * 128;
        for (int i = tid; i < 66 * 128; i += 256) g_xt[r + i] = z;
    }
}

// ============================================================
// Launch 2: router (finalizes stats from partials)
// ============================================================
__global__ void router_kernel(
    const float* __restrict__ time_emb,
    const float* __restrict__ W_q,  const float* __restrict__ W_k,  const float* __restrict__ W_v,
    const float* __restrict__ W_g,  const float* __restrict__ b_g,
    const float* __restrict__ W_a1, const float* __restrict__ b_a1, const float* __restrict__ W_a2,
    const float* __restrict__ W_b1, const float* __restrict__ b_b1, const float* __restrict__ W_b2,
    const float* __restrict__ W_d,  const float* __restrict__ W_out)
{
    int b = blockIdx.x, tid = threadIdx.x;
    __shared__ float te[Tn], sts[2*Cch], xh[HIDn], a1v[GHn], b1v[GHn],
                     tv[Rn], hv[UPn], xm[HIDn], lg[En];
    te[tid] = time_emb[b * Tn + tid];
    if (tid < Cch) {
        float s1 = 0.f, s2 = 0.f;
        for (int y = 0; y < 64; y++) {
            int d = (b * 64 + y) * 128 + tid;
            s1 += g_ps[d]; s2 += g_ps2[d];
        }
        float mu  = s1 * (1.f / 4096.f);
        float var = s2 * (1.f / 4096.f) - mu * mu;
        sts[tid]       = mu;
        sts[Cch + tid] = sqrtf(fmaxf(var, 0.f)) + 1e-6f;
    }
    __syncthreads();
    if (tid < HIDn) {
        float q = 0.f, k = 0.f, v = 0.f;
        for (int j = 0; j < Tn; j++) q += W_q[tid*Tn+j] * te[j];
        for (int j = 0; j < 2*Cch; j++) {
            float s = sts[j];
            k += W_k[tid*2*Cch+j] * s;
            v += W_v[tid*2*Cch+j] * s;
        }
        xh[tid] = v / (1.f + expf(-(q*k)));
    }
    __syncthreads();
    if (tid < GHn) {
        float sa = b_a1[tid], sb = b_b1[tid];
        for (int i = 0; i < HIDn; i++) { sa += W_a1[tid*HIDn+i]*xh[i]; sb += W_b1[tid*HIDn+i]*xh[i]; }
        a1v[tid] = sa / (1.f + expf(-sa));
        b1v[tid] = sb / (1.f + expf(-sb));
    }
    __syncthreads();
    if (tid < Rn) {
        float acc = 0.f;
        for (int i = 0; i < HIDn; i++) {
            const float* wr = W_a2 + (size_t)(i*Rn + tid)*GHn;
            float ai = 0.f;
            #pragma unroll
            for (int g = 0; g < GHn; g++) ai += wr[g]*a1v[g];
            acc += xh[i]*ai;
        }
        tv[tid] = acc;
    }
    __syncthreads();
    {
        float gate = b_g[tid];
        for (int i = 0; i < HIDn; i++) gate += W_g[tid*HIDn+i]*xh[i];
        float dyn = 0.f;
        for (int r = 0; r < Rn; r++) {
            const float* wr = W_b2 + (size_t)(r*UPn + tid)*GHn;
            float bm = 0.f;
            #pragma unroll
            for (int g = 0; g < GHn; g++) bm += wr[g]*b1v[g];
            dyn += tv[r]*bm;
        }
        hv[tid] = (gate / (1.f + expf(-gate))) * dyn;
    }
    __syncthreads();
    if (tid < HIDn) {
        float m = xh[tid];
        for (int o = 0; o < UPn; o++) m += W_d[tid*UPn+o]*hv[o];
        xm[tid] = m;
    }
    __syncthreads();
    if (tid < En) {
        float l = 0.f;
        for (int i = 0; i < HIDn; i++) l += W_out[tid*HIDn+i]*xm[i];
        lg[tid] = l;
    }
    __syncthreads();
    if (tid == 0) {
        float mx = lg[0];
        for (int e = 1; e < En; e++) mx = fmaxf(mx, lg[e]);
        float ex[En]; float s = 0.f;
        for (int e = 0; e < En; e++) { ex[e] = expf(lg[e]-mx); s += ex[e]; }
        float inv = 1.f / s;
        for (int e = 0; e < En; e++) g_rw[b*En+e] = ex[e]*inv;
    }
}

// ============================================================
// Launch 3: mix -> fp16 tiles (x256)  [b][tap][chunk][oc][64c]
// ============================================================
__global__ void mix_kernel(const float* __restrict__ expert_w) {
    __shared__ float srw[Bsz * En];
    int tid = threadIdx.x;
    srw[tid] = g_rw[tid];
    __syncthreads();

    int idx = blockIdx.x * 256 + tid;
    int oc = idx >> 7, c = idx & 127;
    int b0 = blockIdx.y * 8;

    float w[En][9];
    #pragma unroll
    for (int e = 0; e < En; e++) {
        const float* src = expert_w + ((size_t)(e * 128 + oc) * 128 + c) * 9;
        #pragma unroll
        for (int k = 0; k < 9; k++) w[e][k] = src[k];
    }

    int cx = c >> 6, cl = c & 63;
    for (int b = b0; b < b0 + 8; b++) {
        float rw[En];
        #pragma unroll
        for (int e = 0; e < En; e++) rw[e] = srw[b * En + e];
        #pragma unroll
        for (int k = 0; k < 9; k++) {
            float acc = 0.f;
            #pragma unroll
            for (int e = 0; e < En; e++) acc += rw[e] * w[e][k];
            int d = ((b * 9 + k) * 2 + cx) * 8192 + oc * 64 + cl;
            g_wh[d] = __float2half(acc * WSCALE);
        }
    }
}

// ============================================================
// Launch 4: conv via mma.sync fp16
// CTA = (2 image rows, b), 128 threads (2x2 warps), warp tile 64oc x 64px.
// 3 stages x 32KB = 96KB, single __syncthreads per chunk, prefetch dist 2.
// 2 CTAs/SM (regs 21.4K x 2 = 42.8K; smem 96K x 2 = 192K).
// ============================================================
#define STG  32768
#define SA   0
#define SB   16384
#define CONV_SMEM (3*STG)

__global__ void __launch_bounds__(128)
conv_mma_kernel(float* __restrict__ out)
{
    extern __shared__ char dsm[];
    const uint32_t sb = smem_u32(dsm);
    const int tid  = threadIdx.x;
    const int lane = tid & 31;
    const int wid  = tid >> 5;
    const int wm   = wid & 1;          // 64-oc block
    const int wn   = wid >> 1;         // 0..1 : 64-px block (= image row select)
    const int b    = blockIdx.y;
    const int y0   = blockIdx.x * 2;   // two image rows per CTA

    const char* x_base = (const char*)g_xt + (size_t)b * PROWS * 256;

    float acc[4][8][4];
    #pragma unroll
    for (int mi = 0; mi < 4; mi++)
        #pragma unroll
        for (int ni = 0; ni < 8; ni++)
            #pragma unroll
            for (int k = 0; k < 4; k++) acc[mi][ni][k] = 0.f;

    auto load_chunk = [&](int ch, int s) {
        int tap = ch >> 1, cx = ch & 1;
        int dy = tap / 3, dx = tap % 3;
        uint32_t so = sb + s * STG;
        const char* ah = (const char*)g_wh + (size_t)((b*9 + tap)*2 + cx) * 16384;
        for (int i = tid; i < 1024; i += 128) {
            cp16(so + SA + swz((uint32_t)i * 16), ah + i * 16);
        }
        // B: 128 px rows (2 image rows) x 128B
        for (int i = tid; i < 1024; i += 128) {
            int lr = i >> 3, u = i & 7;
            int p = (y0 + (lr >> 6) + dy) * PADW + dx + (lr & 63);
            size_t g = (size_t)p * 256 + cx * 128 + u * 16;
            cp16(so + SB + swz((uint32_t)i * 16), x_base + g);
        }
        cp_commit();
    };

    load_chunk(0, 0);
    load_chunk(1, 1);

    int stage = 0;
    for (int ch = 0; ch < 18; ch++) {
        if (ch < 16) cp_wait1(); else cp_wait0();
        __syncthreads();

        // prefetch ch+2 into stage (stage+2)%3
        if (ch < 16) {
            int ps = stage + 2; if (ps >= 3) ps -= 3;
            load_chunk(ch + 2, ps);
        }

        uint32_t so = sb + stage * STG;
        int arow = wm * 64 + (lane & 15);
        int acol16 = (lane >> 4) * 16;
        int brow = wn * 64 + ((lane >> 4) << 3) + (lane & 7);
        int bcol16 = ((lane >> 3) & 1) * 16;

        #pragma unroll
        for (int ks = 0; ks < 4; ks++) {
            uint32_t ah[4][4], bh[8][2];
            #pragma unroll
            for (int mi = 0; mi < 4; mi++) {
                uint32_t off = swz((uint32_t)(arow + mi * 16) * 128 + ks * 32 + acol16);
                ldsm4(ah[mi], so + SA + off);
            }
            #pragma unroll
            for (int np = 0; np < 4; np++) {
                uint32_t off = swz((uint32_t)(brow + np * 16) * 128 + ks * 32 + bcol16);
                uint32_t t[4];
                ldsm4(t, so + SB + off);
                bh[2*np][0] = t[0]; bh[2*np][1] = t[1];
                bh[2*np+1][0] = t[2]; bh[2*np+1][1] = t[3];
            }
            #pragma unroll
            for (int mi = 0; mi < 4; mi++)
                #pragma unroll
                for (int ni = 0; ni < 8; ni++)
                    mma_fp16(acc[mi][ni], ah[mi], bh[ni]);
        }

        if (++stage == 3) stage = 0;
    }

    // epilogue: y = y0 + wn, x = ni*8 + 2q
    int gid = lane >> 2, q = lane & 3;
    int y = y0 + wn;
    #pragma unroll
    for (int mi = 0; mi < 4; mi++) {
        int oc = wm * 64 + mi * 16 + gid;
        #pragma unroll
        for (int ni = 0; ni < 8; ni++) {
            int xc = ni * 8 + 2 * q;
            size_t base0 = (((size_t)(b * 128 + oc)) * 64 + y) * 64 + xc;
            float2 v0 = make_float2(acc[mi][ni][0] * WSCALE_INV, acc[mi][ni][1] * WSCALE_INV);
            float2 v1 = make_float2(acc[mi][ni][2] * WSCALE_INV, acc[mi][ni][3] * WSCALE_INV);
            *(float2*)(out + base0)          = v0;
            *(float2*)(out + base0 + 8*4096) = v1;   // oc + 8
        }
    }
}

// ============================================================
extern "C" void kernel_launch(void* const* d_in, const int* in_sizes, int n_in,
                              void* d_out, int out_size)
{
    const float* x        = (const float*)d_in[0];
    const float* time_emb = (const float*)d_in[1];
    const float* expert_w = (const float*)d_in[2];
    const float* W_q  = (const float*)d_in[3];
    const float* W_k  = (const float*)d_in[4];
    const float* W_v  = (const float*)d_in[5];
    const float* W_g  = (const float*)d_in[6];
    const float* b_g  = (const float*)d_in[7];
    const float* W_a1 = (const float*)d_in[8];
    const float* b_a1 = (const float*)d_in[9];
    const float* W_a2 = (const float*)d_in[10];
    const float* W_b1 = (const float*)d_in[11];
    const float* b_b1 = (const float*)d_in[12];
    const float* W_b2 = (const float*)d_in[13];
    const float* W_d  = (const float*)d_in[14];
    const float* W_out= (const float*)d_in[15];
    float* out = (float*)d_out;

    cudaFuncSetAttribute(conv_mma_kernel,
                         cudaFuncAttributeMaxDynamicSharedMemorySize, CONV_SMEM);

    prep_kernel<<<dim3(64, Bsz), 256>>>(x);
    router_kernel<<<Bsz, 256>>>(time_emb, W_q, W_k, W_v, W_g, b_g,
                                W_a1, b_a1, W_a2, W_b1, b_b1, W_b2, W_d, W_out);
    mix_kernel<<<dim3(64, 4), 256>>>(expert_w);
    conv_mma_kernel<<<dim3(32, Bsz), 128, CONV_SMEM>>>(out);
}